// round 1
// baseline (speedup 1.0000x reference)
#include <cuda_runtime.h>

// ---------------------------------------------------------------------------
// GNNLayer fused kernel for sm_100a (B200)
//
//   h3 = h @ W_lin + b_lin
//   for k in 0..3:
//     prod = 1
//     for i in 0..1:
//       ht  = concat(h[pairs[k,i]], degrees[k,i])          # [E,131]
//       prod *= sigmoid(ht @ W_tr[k] + b_tr[k])
//       prod *= sigmoid(relu(ht @ W_g1[k] + b_g1[k]) @ W_g2[k] + b_g2[k])
//     h3[scatter_idx[k]] += (1+eps[k]) * prod              # atomic scatter-add
//
// Strategy: fully fused per (key, 128-pair tile) CTA. fp32 math on the packed
// f32x2 FMA pipe (full-rate on Blackwell; scalar FFMA is half-rate).
// ---------------------------------------------------------------------------

#define NN    50000          // nodes
#define D     128            // feature dim (in == out)
#define NK    4              // keys
#define NT    2              // t
#define NE    100000         // pairs per key
#define NOHL  3              // one-hot length
#define KD1   (D + NOHL)     // 131 = contraction dim of first two GEMMs
#define AST   132            // smem row stride (floats) for transposed tiles
#define TILE  128            // pair rows per CTA

// smem sizes (floats)
#define SM_FUSED ((KD1 * AST + D * AST + KD1 * D) * 4)   // 203824 B
#define SM_LIN   ((D * AST + D * D) * 4)                 // 133120 B

static __device__ __forceinline__ float fsig(float x) {
    return 1.0f / (1.0f + __expf(-x));
}

static __device__ __forceinline__ unsigned long long pk2(float lo, float hi) {
    unsigned long long r;
    asm("mov.b64 %0, {%1, %2};" : "=l"(r) : "f"(lo), "f"(hi));
    return r;
}
static __device__ __forceinline__ void upk2(unsigned long long v, float &lo, float &hi) {
    asm("mov.b64 {%0, %1}, %2;" : "=f"(lo), "=f"(hi) : "l"(v));
}
// Packed fp32x2 FMA — the full-rate fp32 path on sm_100 (ptxas never emits it
// from C++; PTX only).
static __device__ __forceinline__ unsigned long long ffma2(unsigned long long a,
                                                           unsigned long long b,
                                                           unsigned long long c) {
    unsigned long long d;
    asm("fma.rn.f32x2 %0, %1, %2, %3;" : "=l"(d) : "l"(a), "l"(b), "l"(c));
    return d;
}

// ---------------------------------------------------------------------------
// 128x128 register-blocked GEMM over a KD-deep contraction.
//   Am: transposed+swizzled activation tile. Logical element (kdim c, row r)
//       lives at Am[c*AST + (r ^ (((c>>3)&7)<<2))]  (XOR swizzle on r bits 2..4,
//       keeps float4 groups contiguous & 16B aligned, kills bank conflicts for
//       the transposed stores that produce the tile).
//   Wm: dense [KD][128] weight tile in smem.
//   Thread (tx,ty) of 16x16 owns rows ty*8..+7, cols tx*8..+7; accumulators are
//   32 f32x2 pairs (col pairs).
// ---------------------------------------------------------------------------
template<int KD>
static __device__ __forceinline__ void gemm_f2(const float* __restrict__ Am,
                                               const float* __restrict__ Wm,
                                               unsigned long long (&acc)[8][4],
                                               int tx, int ty)
{
    #pragma unroll
    for (int j = 0; j < 8; ++j)
        #pragma unroll
        for (int l = 0; l < 4; ++l) acc[j][l] = 0ull;

    const int x = ty * 8;
    #pragma unroll 2
    for (int kk = 0; kk < KD; ++kk) {
        const int s4 = ((kk >> 3) & 7) << 2;
        const int r0 = x ^ s4;
        const float4 a0 = *(const float4*)(Am + kk * AST + r0);        // rows x..x+3
        const float4 a1 = *(const float4*)(Am + kk * AST + (r0 ^ 4));  // rows x+4..x+7
        const float4 b0 = *(const float4*)(Wm + kk * D + tx * 8);
        const float4 b1 = *(const float4*)(Wm + kk * D + tx * 8 + 4);
        const unsigned long long bp0 = pk2(b0.x, b0.y);
        const unsigned long long bp1 = pk2(b0.z, b0.w);
        const unsigned long long bp2 = pk2(b1.x, b1.y);
        const unsigned long long bp3 = pk2(b1.z, b1.w);
        const float av[8] = {a0.x, a0.y, a0.z, a0.w, a1.x, a1.y, a1.z, a1.w};
        #pragma unroll
        for (int j = 0; j < 8; ++j) {
            const unsigned long long ap = pk2(av[j], av[j]);
            acc[j][0] = ffma2(ap, bp0, acc[j][0]);
            acc[j][1] = ffma2(ap, bp1, acc[j][1]);
            acc[j][2] = ffma2(ap, bp2, acc[j][2]);
            acc[j][3] = ffma2(ap, bp3, acc[j][3]);
        }
    }
}

// prod[j][l] *= sigmoid(acc + bias)
static __device__ __forceinline__ void prod_sig(const unsigned long long (&acc)[8][4],
                                                float (&prod)[8][8],
                                                const float* __restrict__ bias,
                                                int tx)
{
    #pragma unroll
    for (int l = 0; l < 4; ++l) {
        const float bl = bias[tx * 8 + 2 * l];
        const float bh = bias[tx * 8 + 2 * l + 1];
        #pragma unroll
        for (int j = 0; j < 8; ++j) {
            float lo, hi; upk2(acc[j][l], lo, hi);
            prod[j][2 * l]     *= fsig(lo + bl);
            prod[j][2 * l + 1] *= fsig(hi + bh);
        }
    }
}

// ---------------------------------------------------------------------------
// Kernel 1: h3 = h @ W_lin + b_lin   (also initializes d_out everywhere)
// ---------------------------------------------------------------------------
__global__ void __launch_bounds__(256, 1)
gnn_lin_kernel(const float* __restrict__ h, const float* __restrict__ W,
               const float* __restrict__ b, float* __restrict__ out)
{
    extern __shared__ float sm[];
    float* As = sm;               // [D][AST] transposed/swizzled
    float* Ws = As + D * AST;     // [D][D]

    const int tid = threadIdx.x;
    const int tx  = tid & 15;
    const int ty  = tid >> 4;
    const int r0  = blockIdx.x * TILE;

    // gather rows (2 threads per row, 64 floats each)
    {
        const int r = tid >> 1;
        const int half = tid & 1;
        const int row = r0 + r;
        if (row < NN) {
            const float4* hrow = (const float4*)(h + row * D) + half * 16;
            #pragma unroll
            for (int q = 0; q < 16; ++q) {
                const float4 v = hrow[q];
                const int c  = half * 64 + q * 4;
                const int pr = r ^ (((c >> 3) & 7) << 2);
                float* dst = As + c * AST + pr;
                dst[0]       = v.x;
                dst[AST]     = v.y;
                dst[2 * AST] = v.z;
                dst[3 * AST] = v.w;
            }
        } else {
            #pragma unroll
            for (int q = 0; q < 16; ++q) {
                const int c  = half * 64 + q * 4;
                const int pr = r ^ (((c >> 3) & 7) << 2);
                float* dst = As + c * AST + pr;
                dst[0] = 0.f; dst[AST] = 0.f; dst[2 * AST] = 0.f; dst[3 * AST] = 0.f;
            }
        }
    }
    // copy W
    {
        const float4* src = (const float4*)W;
        float4* d4 = (float4*)Ws;
        #pragma unroll 4
        for (int i = tid; i < (D * D) / 4; i += 256) d4[i] = src[i];
    }
    __syncthreads();

    unsigned long long acc[8][4];
    gemm_f2<D>(As, Ws, acc, tx, ty);

    #pragma unroll
    for (int j = 0; j < 8; ++j) {
        const int row = r0 + ty * 8 + j;
        if (row < NN) {
            float o[8];
            #pragma unroll
            for (int l = 0; l < 4; ++l) {
                float lo, hi; upk2(acc[j][l], lo, hi);
                o[2 * l]     = lo + b[tx * 8 + 2 * l];
                o[2 * l + 1] = hi + b[tx * 8 + 2 * l + 1];
            }
            float4* dst = (float4*)(out + row * D + tx * 8);
            dst[0] = make_float4(o[0], o[1], o[2], o[3]);
            dst[1] = make_float4(o[4], o[5], o[6], o[7]);
        }
    }
}

// ---------------------------------------------------------------------------
// Kernel 2: fused per-key message kernel. grid = (ceil(E/128), K)
// ---------------------------------------------------------------------------
__global__ void __launch_bounds__(256, 1)
gnn_fused_kernel(const float* __restrict__ h,
                 const int*   __restrict__ pairs,
                 const float* __restrict__ degrees,
                 const int*   __restrict__ scat,
                 const float* __restrict__ W_tr, const float* __restrict__ b_tr,
                 const float* __restrict__ W_g1, const float* __restrict__ b_g1,
                 const float* __restrict__ W_g2, const float* __restrict__ b_g2,
                 const float* __restrict__ eps,
                 float* __restrict__ out)
{
    extern __shared__ float sm[];
    float* As = sm;                   // [KD1][AST] gathered ht, transposed/swizzled
    float* Bs = As + KD1 * AST;       // [D][AST]   relu(ht@Wg1+b), transposed/swizzled
    float* Ws = Bs + D * AST;         // [KD1][D]   streamed weight buffer

    const int tid = threadIdx.x;
    const int tx  = tid & 15;
    const int ty  = tid >> 4;
    const int e0  = blockIdx.x * TILE;
    const int k   = blockIdx.y;

    float prod[8][8];
    #pragma unroll
    for (int j = 0; j < 8; ++j)
        #pragma unroll
        for (int l = 0; l < 8; ++l) prod[j][l] = 1.0f;

    unsigned long long acc[8][4];

    for (int it = 0; it < NT; ++it) {
        __syncthreads();   // prior iter's reads of As/Bs complete
        // ---- gather ht tile: h[pairs[k,it,e]] ++ degrees[k,it,e] ----
        {
            const int r = tid >> 1;
            const int half = tid & 1;
            const int e = e0 + r;
            if (e < NE) {
                const int idx = pairs[(k * NT + it) * NE + e];
                const float4* hrow = (const float4*)(h + idx * D) + half * 16;
                #pragma unroll
                for (int q = 0; q < 16; ++q) {
                    const float4 v = hrow[q];
                    const int c  = half * 64 + q * 4;
                    const int pr = r ^ (((c >> 3) & 7) << 2);
                    float* dst = As + c * AST + pr;
                    dst[0]       = v.x;
                    dst[AST]     = v.y;
                    dst[2 * AST] = v.z;
                    dst[3 * AST] = v.w;
                }
                if (half == 0) {
                    const float* dg = degrees + ((k * NT + it) * NE + e) * NOHL;
                    As[(D + 0) * AST + r] = dg[0];
                    As[(D + 1) * AST + r] = dg[1];
                    As[(D + 2) * AST + r] = dg[2];
                }
            } else {
                #pragma unroll
                for (int q = 0; q < 16; ++q) {
                    const int c  = half * 64 + q * 4;
                    const int pr = r ^ (((c >> 3) & 7) << 2);
                    float* dst = As + c * AST + pr;
                    dst[0] = 0.f; dst[AST] = 0.f; dst[2 * AST] = 0.f; dst[3 * AST] = 0.f;
                }
                if (half == 0) {
                    As[(D + 0) * AST + r] = 0.f;
                    As[(D + 1) * AST + r] = 0.f;
                    As[(D + 2) * AST + r] = 0.f;
                }
            }
        }
        // ---- W <- W_g1[k] ----
        {
            const float4* src = (const float4*)(W_g1 + k * KD1 * D);
            float4* d4 = (float4*)Ws;
            #pragma unroll 4
            for (int i = tid; i < (KD1 * D) / 4; i += 256) d4[i] = src[i];
        }
        __syncthreads();

        // ---- GEMM1: g1 = relu(ht @ W_g1 + b_g1) -> Bs (transposed/swizzled) ----
        gemm_f2<KD1>(As, Ws, acc, tx, ty);
        {
            const float* bb = b_g1 + k * D;
            #pragma unroll
            for (int l = 0; l < 4; ++l) {
                const int c0 = tx * 8 + 2 * l;
                const float bl = bb[c0];
                const float bh = bb[c0 + 1];
                #pragma unroll
                for (int j = 0; j < 8; ++j) {
                    float lo, hi; upk2(acc[j][l], lo, hi);
                    const int pr = (ty * 8 + j) ^ ((tx & 7) << 2);
                    const float v0 = lo + bl;
                    const float v1 = hi + bh;
                    Bs[c0 * AST + pr]       = v0 > 0.f ? v0 : 0.f;
                    Bs[(c0 + 1) * AST + pr] = v1 > 0.f ? v1 : 0.f;
                }
            }
        }
        __syncthreads();   // Ws free, Bs visible

        // ---- W <- W_tr[k]; GEMM2: prod *= sigmoid(ht @ W_tr + b_tr) ----
        {
            const float4* src = (const float4*)(W_tr + k * KD1 * D);
            float4* d4 = (float4*)Ws;
            #pragma unroll 4
            for (int i = tid; i < (KD1 * D) / 4; i += 256) d4[i] = src[i];
        }
        __syncthreads();
        gemm_f2<KD1>(As, Ws, acc, tx, ty);
        prod_sig(acc, prod, b_tr + k * D, tx);
        __syncthreads();   // Ws free

        // ---- W <- W_g2[k]; GEMM3: prod *= sigmoid(g1 @ W_g2 + b_g2) ----
        {
            const float4* src = (const float4*)(W_g2 + k * D * D);
            float4* d4 = (float4*)Ws;
            #pragma unroll 4
            for (int i = tid; i < (D * D) / 4; i += 256) d4[i] = src[i];
        }
        __syncthreads();
        gemm_f2<D>(Bs, Ws, acc, tx, ty);
        prod_sig(acc, prod, b_g2 + k * D, tx);
    }

    // ---- scatter-add: out[scatter_idx[k,e]] += (1+eps[k]) * prod ----
    const float scale = 1.0f + eps[k];
    #pragma unroll
    for (int j = 0; j < 8; ++j) {
        const int e = e0 + ty * 8 + j;
        if (e < NE) {
            const int idx = scat[k * NE + e];
            float* dst = out + idx * D + tx * 8;
            asm volatile("red.global.add.v4.f32 [%0], {%1,%2,%3,%4};"
                         :: "l"(dst),
                            "f"(prod[j][0] * scale), "f"(prod[j][1] * scale),
                            "f"(prod[j][2] * scale), "f"(prod[j][3] * scale)
                         : "memory");
            asm volatile("red.global.add.v4.f32 [%0], {%1,%2,%3,%4};"
                         :: "l"(dst + 4),
                            "f"(prod[j][4] * scale), "f"(prod[j][5] * scale),
                            "f"(prod[j][6] * scale), "f"(prod[j][7] * scale)
                         : "memory");
        }
    }
}

// ---------------------------------------------------------------------------
extern "C" void kernel_launch(void* const* d_in, const int* in_sizes, int n_in,
                              void* d_out, int out_size)
{
    const float* h       = (const float*)d_in[0];
    const int*   pairs   = (const int*)  d_in[1];
    const float* degrees = (const float*)d_in[2];
    const int*   scat    = (const int*)  d_in[3];
    const float* W_lin   = (const float*)d_in[4];
    const float* b_lin   = (const float*)d_in[5];
    const float* W_tr    = (const float*)d_in[6];
    const float* b_tr    = (const float*)d_in[7];
    const float* W_g1    = (const float*)d_in[8];
    const float* b_g1    = (const float*)d_in[9];
    const float* W_g2    = (const float*)d_in[10];
    const float* b_g2    = (const float*)d_in[11];
    const float* eps     = (const float*)d_in[12];
    float* out = (float*)d_out;

    cudaFuncSetAttribute(gnn_lin_kernel,
                         cudaFuncAttributeMaxDynamicSharedMemorySize, SM_LIN);
    cudaFuncSetAttribute(gnn_fused_kernel,
                         cudaFuncAttributeMaxDynamicSharedMemorySize, SM_FUSED);

    gnn_lin_kernel<<<(NN + TILE - 1) / TILE, 256, SM_LIN>>>(h, W_lin, b_lin, out);

    dim3 grid((NE + TILE - 1) / TILE, NK);
    gnn_fused_kernel<<<grid, 256, SM_FUSED>>>(h, pairs, degrees, scat,
                                              W_tr, b_tr, W_g1, b_g1,
                                              W_g2, b_g2, eps, out);
}

// round 2
// speedup vs baseline: 1.0007x; 1.0007x over previous
#include <cuda_runtime.h>

// ---------------------------------------------------------------------------
// GNNLayer fused kernel for sm_100a (B200)
//
//   h3 = h @ W_lin + b_lin
//   for k in 0..3:
//     prod = 1
//     for i in 0..1:
//       ht  = concat(h[pairs[k,i]], degrees[k,i])          # [E,131]
//       prod *= sigmoid(ht @ W_tr[k] + b_tr[k])
//       prod *= sigmoid(relu(ht @ W_g1[k] + b_g1[k]) @ W_g2[k] + b_g2[k])
//     h3[scatter_idx[k]] += (1+eps[k]) * prod              # atomic scatter-add
//
// Strategy: fully fused per (key, 128-pair tile) CTA. fp32 math on the packed
// f32x2 FMA pipe (full-rate on Blackwell; scalar FFMA is half-rate).
// ---------------------------------------------------------------------------

#define NN    50000          // nodes
#define D     128            // feature dim (in == out)
#define NK    4              // keys
#define NT    2              // t
#define NE    100000         // pairs per key
#define NOHL  3              // one-hot length
#define KD1   (D + NOHL)     // 131 = contraction dim of first two GEMMs
#define AST   132            // smem row stride (floats) for transposed tiles
#define TILE  128            // pair rows per CTA

// smem sizes (floats)
#define SM_FUSED ((KD1 * AST + D * AST + KD1 * D) * 4)   // 203824 B
#define SM_LIN   ((D * AST + D * D) * 4)                 // 133120 B

static __device__ __forceinline__ float fsig(float x) {
    return 1.0f / (1.0f + __expf(-x));
}

static __device__ __forceinline__ unsigned long long pk2(float lo, float hi) {
    unsigned long long r;
    asm("mov.b64 %0, {%1, %2};" : "=l"(r) : "f"(lo), "f"(hi));
    return r;
}
static __device__ __forceinline__ void upk2(unsigned long long v, float &lo, float &hi) {
    asm("mov.b64 {%0, %1}, %2;" : "=f"(lo), "=f"(hi) : "l"(v));
}
// Packed fp32x2 FMA — the full-rate fp32 path on sm_100 (ptxas never emits it
// from C++; PTX only).
static __device__ __forceinline__ unsigned long long ffma2(unsigned long long a,
                                                           unsigned long long b,
                                                           unsigned long long c) {
    unsigned long long d;
    asm("fma.rn.f32x2 %0, %1, %2, %3;" : "=l"(d) : "l"(a), "l"(b), "l"(c));
    return d;
}

// ---------------------------------------------------------------------------
// 128x128 register-blocked GEMM over a KD-deep contraction.
//   Am: transposed+swizzled activation tile. Logical element (kdim c, row r)
//       lives at Am[c*AST + (r ^ (((c>>3)&7)<<2))]  (XOR swizzle on r bits 2..4,
//       keeps float4 groups contiguous & 16B aligned, kills bank conflicts for
//       the transposed stores that produce the tile).
//   Wm: dense [KD][128] weight tile in smem.
//   Thread (tx,ty) of 16x16 owns rows ty*8..+7, cols tx*8..+7; accumulators are
//   32 f32x2 pairs (col pairs).
// ---------------------------------------------------------------------------
template<int KD>
static __device__ __forceinline__ void gemm_f2(const float* __restrict__ Am,
                                               const float* __restrict__ Wm,
                                               unsigned long long (&acc)[8][4],
                                               int tx, int ty)
{
    #pragma unroll
    for (int j = 0; j < 8; ++j)
        #pragma unroll
        for (int l = 0; l < 4; ++l) acc[j][l] = 0ull;

    const int x = ty * 8;
    #pragma unroll 2
    for (int kk = 0; kk < KD; ++kk) {
        const int s4 = ((kk >> 3) & 7) << 2;
        const int r0 = x ^ s4;
        const float4 a0 = *(const float4*)(Am + kk * AST + r0);        // rows x..x+3
        const float4 a1 = *(const float4*)(Am + kk * AST + (r0 ^ 4));  // rows x+4..x+7
        const float4 b0 = *(const float4*)(Wm + kk * D + tx * 8);
        const float4 b1 = *(const float4*)(Wm + kk * D + tx * 8 + 4);
        const unsigned long long bp0 = pk2(b0.x, b0.y);
        const unsigned long long bp1 = pk2(b0.z, b0.w);
        const unsigned long long bp2 = pk2(b1.x, b1.y);
        const unsigned long long bp3 = pk2(b1.z, b1.w);
        const float av[8] = {a0.x, a0.y, a0.z, a0.w, a1.x, a1.y, a1.z, a1.w};
        #pragma unroll
        for (int j = 0; j < 8; ++j) {
            const unsigned long long ap = pk2(av[j], av[j]);
            acc[j][0] = ffma2(ap, bp0, acc[j][0]);
            acc[j][1] = ffma2(ap, bp1, acc[j][1]);
            acc[j][2] = ffma2(ap, bp2, acc[j][2]);
            acc[j][3] = ffma2(ap, bp3, acc[j][3]);
        }
    }
}

// prod[j][l] *= sigmoid(acc + bias)
static __device__ __forceinline__ void prod_sig(const unsigned long long (&acc)[8][4],
                                                float (&prod)[8][8],
                                                const float* __restrict__ bias,
                                                int tx)
{
    #pragma unroll
    for (int l = 0; l < 4; ++l) {
        const float bl = bias[tx * 8 + 2 * l];
        const float bh = bias[tx * 8 + 2 * l + 1];
        #pragma unroll
        for (int j = 0; j < 8; ++j) {
            float lo, hi; upk2(acc[j][l], lo, hi);
            prod[j][2 * l]     *= fsig(lo + bl);
            prod[j][2 * l + 1] *= fsig(hi + bh);
        }
    }
}

// ---------------------------------------------------------------------------
// Kernel 1: h3 = h @ W_lin + b_lin   (also initializes d_out everywhere)
// ---------------------------------------------------------------------------
__global__ void __launch_bounds__(256, 1)
gnn_lin_kernel(const float* __restrict__ h, const float* __restrict__ W,
               const float* __restrict__ b, float* __restrict__ out)
{
    extern __shared__ float sm[];
    float* As = sm;               // [D][AST] transposed/swizzled
    float* Ws = As + D * AST;     // [D][D]

    const int tid = threadIdx.x;
    const int tx  = tid & 15;
    const int ty  = tid >> 4;
    const int r0  = blockIdx.x * TILE;

    // gather rows (2 threads per row, 64 floats each)
    {
        const int r = tid >> 1;
        const int half = tid & 1;
        const int row = r0 + r;
        if (row < NN) {
            const float4* hrow = (const float4*)(h + row * D) + half * 16;
            #pragma unroll
            for (int q = 0; q < 16; ++q) {
                const float4 v = hrow[q];
                const int c  = half * 64 + q * 4;
                const int pr = r ^ (((c >> 3) & 7) << 2);
                float* dst = As + c * AST + pr;
                dst[0]       = v.x;
                dst[AST]     = v.y;
                dst[2 * AST] = v.z;
                dst[3 * AST] = v.w;
            }
        } else {
            #pragma unroll
            for (int q = 0; q < 16; ++q) {
                const int c  = half * 64 + q * 4;
                const int pr = r ^ (((c >> 3) & 7) << 2);
                float* dst = As + c * AST + pr;
                dst[0] = 0.f; dst[AST] = 0.f; dst[2 * AST] = 0.f; dst[3 * AST] = 0.f;
            }
        }
    }
    // copy W
    {
        const float4* src = (const float4*)W;
        float4* d4 = (float4*)Ws;
        #pragma unroll 4
        for (int i = tid; i < (D * D) / 4; i += 256) d4[i] = src[i];
    }
    __syncthreads();

    unsigned long long acc[8][4];
    gemm_f2<D>(As, Ws, acc, tx, ty);

    #pragma unroll
    for (int j = 0; j < 8; ++j) {
        const int row = r0 + ty * 8 + j;
        if (row < NN) {
            float o[8];
            #pragma unroll
            for (int l = 0; l < 4; ++l) {
                float lo, hi; upk2(acc[j][l], lo, hi);
                o[2 * l]     = lo + b[tx * 8 + 2 * l];
                o[2 * l + 1] = hi + b[tx * 8 + 2 * l + 1];
            }
            float4* dst = (float4*)(out + row * D + tx * 8);
            dst[0] = make_float4(o[0], o[1], o[2], o[3]);
            dst[1] = make_float4(o[4], o[5], o[6], o[7]);
        }
    }
}

// ---------------------------------------------------------------------------
// Kernel 2: fused per-key message kernel. grid = (ceil(E/128), K)
// ---------------------------------------------------------------------------
__global__ void __launch_bounds__(256, 1)
gnn_fused_kernel(const float* __restrict__ h,
                 const int*   __restrict__ pairs,
                 const float* __restrict__ degrees,
                 const int*   __restrict__ scat,
                 const float* __restrict__ W_tr, const float* __restrict__ b_tr,
                 const float* __restrict__ W_g1, const float* __restrict__ b_g1,
                 const float* __restrict__ W_g2, const float* __restrict__ b_g2,
                 const float* __restrict__ eps,
                 float* __restrict__ out)
{
    extern __shared__ float sm[];
    float* As = sm;                   // [KD1][AST] gathered ht, transposed/swizzled
    float* Bs = As + KD1 * AST;       // [D][AST]   relu(ht@Wg1+b), transposed/swizzled
    float* Ws = Bs + D * AST;         // [KD1][D]   streamed weight buffer

    const int tid = threadIdx.x;
    const int tx  = tid & 15;
    const int ty  = tid >> 4;
    const int e0  = blockIdx.x * TILE;
    const int k   = blockIdx.y;

    float prod[8][8];
    #pragma unroll
    for (int j = 0; j < 8; ++j)
        #pragma unroll
        for (int l = 0; l < 8; ++l) prod[j][l] = 1.0f;

    unsigned long long acc[8][4];

    for (int it = 0; it < NT; ++it) {
        __syncthreads();   // prior iter's reads of As/Bs complete
        // ---- gather ht tile: h[pairs[k,it,e]] ++ degrees[k,it,e] ----
        {
            const int r = tid >> 1;
            const int half = tid & 1;
            const int e = e0 + r;
            if (e < NE) {
                const int idx = pairs[(k * NT + it) * NE + e];
                const float4* hrow = (const float4*)(h + idx * D) + half * 16;
                #pragma unroll
                for (int q = 0; q < 16; ++q) {
                    const float4 v = hrow[q];
                    const int c  = half * 64 + q * 4;
                    const int pr = r ^ (((c >> 3) & 7) << 2);
                    float* dst = As + c * AST + pr;
                    dst[0]       = v.x;
                    dst[AST]     = v.y;
                    dst[2 * AST] = v.z;
                    dst[3 * AST] = v.w;
                }
                if (half == 0) {
                    const float* dg = degrees + ((k * NT + it) * NE + e) * NOHL;
                    As[(D + 0) * AST + r] = dg[0];
                    As[(D + 1) * AST + r] = dg[1];
                    As[(D + 2) * AST + r] = dg[2];
                }
            } else {
                #pragma unroll
                for (int q = 0; q < 16; ++q) {
                    const int c  = half * 64 + q * 4;
                    const int pr = r ^ (((c >> 3) & 7) << 2);
                    float* dst = As + c * AST + pr;
                    dst[0] = 0.f; dst[AST] = 0.f; dst[2 * AST] = 0.f; dst[3 * AST] = 0.f;
                }
                if (half == 0) {
                    As[(D + 0) * AST + r] = 0.f;
                    As[(D + 1) * AST + r] = 0.f;
                    As[(D + 2) * AST + r] = 0.f;
                }
            }
        }
        // ---- W <- W_g1[k] ----
        {
            const float4* src = (const float4*)(W_g1 + k * KD1 * D);
            float4* d4 = (float4*)Ws;
            #pragma unroll 4
            for (int i = tid; i < (KD1 * D) / 4; i += 256) d4[i] = src[i];
        }
        __syncthreads();

        // ---- GEMM1: g1 = relu(ht @ W_g1 + b_g1) -> Bs (transposed/swizzled) ----
        gemm_f2<KD1>(As, Ws, acc, tx, ty);
        {
            const float* bb = b_g1 + k * D;
            #pragma unroll
            for (int l = 0; l < 4; ++l) {
                const int c0 = tx * 8 + 2 * l;
                const float bl = bb[c0];
                const float bh = bb[c0 + 1];
                #pragma unroll
                for (int j = 0; j < 8; ++j) {
                    float lo, hi; upk2(acc[j][l], lo, hi);
                    const int pr = (ty * 8 + j) ^ ((tx & 7) << 2);
                    const float v0 = lo + bl;
                    const float v1 = hi + bh;
                    Bs[c0 * AST + pr]       = v0 > 0.f ? v0 : 0.f;
                    Bs[(c0 + 1) * AST + pr] = v1 > 0.f ? v1 : 0.f;
                }
            }
        }
        __syncthreads();   // Ws free, Bs visible

        // ---- W <- W_tr[k]; GEMM2: prod *= sigmoid(ht @ W_tr + b_tr) ----
        {
            const float4* src = (const float4*)(W_tr + k * KD1 * D);
            float4* d4 = (float4*)Ws;
            #pragma unroll 4
            for (int i = tid; i < (KD1 * D) / 4; i += 256) d4[i] = src[i];
        }
        __syncthreads();
        gemm_f2<KD1>(As, Ws, acc, tx, ty);
        prod_sig(acc, prod, b_tr + k * D, tx);
        __syncthreads();   // Ws free

        // ---- W <- W_g2[k]; GEMM3: prod *= sigmoid(g1 @ W_g2 + b_g2) ----
        {
            const float4* src = (const float4*)(W_g2 + k * D * D);
            float4* d4 = (float4*)Ws;
            #pragma unroll 4
            for (int i = tid; i < (D * D) / 4; i += 256) d4[i] = src[i];
        }
        __syncthreads();
        gemm_f2<D>(Bs, Ws, acc, tx, ty);
        prod_sig(acc, prod, b_g2 + k * D, tx);
    }

    // ---- scatter-add: out[scatter_idx[k,e]] += (1+eps[k]) * prod ----
    const float scale = 1.0f + eps[k];
    #pragma unroll
    for (int j = 0; j < 8; ++j) {
        const int e = e0 + ty * 8 + j;
        if (e < NE) {
            const int idx = scat[k * NE + e];
            float* dst = out + idx * D + tx * 8;
            asm volatile("red.global.add.v4.f32 [%0], {%1,%2,%3,%4};"
                         :: "l"(dst),
                            "f"(prod[j][0] * scale), "f"(prod[j][1] * scale),
                            "f"(prod[j][2] * scale), "f"(prod[j][3] * scale)
                         : "memory");
            asm volatile("red.global.add.v4.f32 [%0], {%1,%2,%3,%4};"
                         :: "l"(dst + 4),
                            "f"(prod[j][4] * scale), "f"(prod[j][5] * scale),
                            "f"(prod[j][6] * scale), "f"(prod[j][7] * scale)
                         : "memory");
        }
    }
}

// ---------------------------------------------------------------------------
extern "C" void kernel_launch(void* const* d_in, const int* in_sizes, int n_in,
                              void* d_out, int out_size)
{
    const float* h       = (const float*)d_in[0];
    const int*   pairs   = (const int*)  d_in[1];
    const float* degrees = (const float*)d_in[2];
    const int*   scat    = (const int*)  d_in[3];
    const float* W_lin   = (const float*)d_in[4];
    const float* b_lin   = (const float*)d_in[5];
    const float* W_tr    = (const float*)d_in[6];
    const float* b_tr    = (const float*)d_in[7];
    const float* W_g1    = (const float*)d_in[8];
    const float* b_g1    = (const float*)d_in[9];
    const float* W_g2    = (const float*)d_in[10];
    const float* b_g2    = (const float*)d_in[11];
    const float* eps     = (const float*)d_in[12];
    float* out = (float*)d_out;

    cudaFuncSetAttribute(gnn_lin_kernel,
                         cudaFuncAttributeMaxDynamicSharedMemorySize, SM_LIN);
    cudaFuncSetAttribute(gnn_fused_kernel,
                         cudaFuncAttributeMaxDynamicSharedMemorySize, SM_FUSED);

    gnn_lin_kernel<<<(NN + TILE - 1) / TILE, 256, SM_LIN>>>(h, W_lin, b_lin, out);

    dim3 grid((NE + TILE - 1) / TILE, NK);
    gnn_fused_kernel<<<grid, 256, SM_FUSED>>>(h, pairs, degrees, scat,
                                              W_tr, b_tr, W_g1, b_g1,
                                              W_g2, b_g2, eps, out);
}

// round 4
// speedup vs baseline: 1.1202x; 1.1194x over previous
#include <cuda_runtime.h>
#include <cstdint>

#define NN    50000
#define D     128
#define NK    4
#define NT    2
#define NE    100000
#define NOHL  3
#define KD1   (D + NOHL)     // 131
#define AST   132            // transposed-tile row stride (floats)
#define TILE  128

#define SM_FUSED ((KD1 * AST + D * AST + KD1 * D) * 4)
#define SM_LIN   ((D * AST + D * D) * 4)

typedef unsigned long long ull;

static __device__ __forceinline__ float fsig(float x) {
    return 1.0f / (1.0f + __expf(-x));
}
static __device__ __forceinline__ ull dup2(float v) {
    ull r; asm("mov.b64 %0, {%1, %1};" : "=l"(r) : "f"(v)); return r;
}
static __device__ __forceinline__ void upk2(ull v, float &lo, float &hi) {
    asm("mov.b64 {%0, %1}, %2;" : "=f"(lo), "=f"(hi) : "l"(v));
}
static __device__ __forceinline__ ull ffma2(ull a, ull b, ull c) {
    ull d; asm("fma.rn.f32x2 %0, %1, %2, %3;" : "=l"(d) : "l"(a), "l"(b), "l"(c));
    return d;
}
static __device__ __forceinline__ void cp16(unsigned s, const void* g) {
    asm volatile("cp.async.cg.shared.global [%0], [%1], 16;" :: "r"(s), "l"(g));
}
static __device__ __forceinline__ void cp_fence() {
    asm volatile("cp.async.commit_group;\n\tcp.async.wait_group 0;" ::: "memory");
}
// contiguous weight copy: n16 16-byte chunks
static __device__ __forceinline__ void wcopy(float* dst, const float* __restrict__ src,
                                             int n16, int tid) {
    unsigned d0 = (unsigned)__cvta_generic_to_shared(dst);
    for (int i = tid; i < n16; i += 256)
        cp16(d0 + (unsigned)i * 16u, (const char*)src + (size_t)i * 16);
}

// ---------------------------------------------------------------------------
// Row-pair-packed 128x128 GEMM over transposed+swizzled A tile.
//   A element (kdim kk, row r) at A[kk*AST + (r ^ (((kk>>3)&7)<<2))].
//   W dense [KD][128]. Thread (tx,ty): rows x..x+7 (x=ty*8) as 4 packed pairs,
//   cols {4tx..4tx+3, 64+4tx..64+4tx+3}. acc[rp][q]: lo=row x+2rp, hi=row x+2rp+1.
// ---------------------------------------------------------------------------
template<int KD>
static __device__ __forceinline__ void gemm_rp(const float* __restrict__ A,
                                               const float* __restrict__ W,
                                               ull (&acc)[4][8], int x, int tx)
{
    #pragma unroll
    for (int rp = 0; rp < 4; ++rp)
        #pragma unroll
        for (int q = 0; q < 8; ++q) acc[rp][q] = 0ull;

    #pragma unroll 4
    for (int kk = 0; kk < KD; ++kk) {
        const int r0 = x ^ (((kk >> 3) & 7) << 2);
        const float* Ar = A + kk * AST;
        const ulonglong2 a01 = *(const ulonglong2*)(Ar + r0);
        const ulonglong2 a23 = *(const ulonglong2*)(Ar + (r0 ^ 4));
        const float4 b0 = *(const float4*)(W + kk * D + 4 * tx);
        const float4 b1 = *(const float4*)(W + kk * D + 64 + 4 * tx);
        const ull bd[8] = {dup2(b0.x), dup2(b0.y), dup2(b0.z), dup2(b0.w),
                           dup2(b1.x), dup2(b1.y), dup2(b1.z), dup2(b1.w)};
        const ull ap[4] = {a01.x, a01.y, a23.x, a23.y};
        #pragma unroll
        for (int rp = 0; rp < 4; ++rp)
            #pragma unroll
            for (int q = 0; q < 8; ++q)
                acc[rp][q] = ffma2(ap[rp], bd[q], acc[rp][q]);
    }
}

// gather one 128-row tile of h (+optional zero-pad) into transposed As
static __device__ __forceinline__ void gather_rows(float* As, const float* __restrict__ h,
                                                   int row, int r, int half)
{
    if (row >= 0) {
        const float4* hrow = (const float4*)(h + (size_t)row * D) + half * 16;
        #pragma unroll
        for (int q = 0; q < 16; ++q) {
            const float4 v = hrow[q];
            const int c  = half * 64 + q * 4;
            const int pr = r ^ (((c >> 3) & 7) << 2);
            float* dst = As + c * AST + pr;
            dst[0] = v.x; dst[AST] = v.y; dst[2 * AST] = v.z; dst[3 * AST] = v.w;
        }
    } else {
        #pragma unroll
        for (int q = 0; q < 16; ++q) {
            const int c  = half * 64 + q * 4;
            const int pr = r ^ (((c >> 3) & 7) << 2);
            float* dst = As + c * AST + pr;
            dst[0] = 0.f; dst[AST] = 0.f; dst[2 * AST] = 0.f; dst[3 * AST] = 0.f;
        }
    }
}

// prod[j][q] *= sigmoid(acc + bias)
static __device__ __forceinline__ void prod_sig(const ull (&acc)[4][8],
                                                float (&prod)[8][8],
                                                const float* __restrict__ bias, int tx)
{
    const float4 bL = *(const float4*)(bias + 4 * tx);
    const float4 bH = *(const float4*)(bias + 64 + 4 * tx);
    const float bq[8] = {bL.x, bL.y, bL.z, bL.w, bH.x, bH.y, bH.z, bH.w};
    #pragma unroll
    for (int q = 0; q < 8; ++q)
        #pragma unroll
        for (int rp = 0; rp < 4; ++rp) {
            float lo, hi; upk2(acc[rp][q], lo, hi);
            prod[2 * rp][q]     *= fsig(lo + bq[q]);
            prod[2 * rp + 1][q] *= fsig(hi + bq[q]);
        }
}

// ---------------------------------------------------------------------------
// Kernel 1: h3 = h @ W_lin + b_lin (initializes all of d_out)
// ---------------------------------------------------------------------------
__global__ void __launch_bounds__(256, 1)
gnn_lin_kernel(const float* __restrict__ h, const float* __restrict__ W,
               const float* __restrict__ b, float* __restrict__ out)
{
    extern __shared__ float sm[];
    float* As = sm;               // [D][AST]
    float* Ws = As + D * AST;     // [D][D]

    const int tid = threadIdx.x;
    const int tx  = tid & 15;
    const int x   = (tid >> 4) * 8;
    const int r0  = blockIdx.x * TILE;

    {
        const int r = tid >> 1, half = tid & 1;
        const int row = r0 + r;
        gather_rows(As, h, row < NN ? row : -1, r, half);
    }
    wcopy(Ws, W, D * D / 4, tid);
    cp_fence();
    __syncthreads();

    ull acc[4][8];
    gemm_rp<D>(As, Ws, acc, x, tx);

    const float4 bL = *(const float4*)(b + 4 * tx);
    const float4 bH = *(const float4*)(b + 64 + 4 * tx);
    const float bq[8] = {bL.x, bL.y, bL.z, bL.w, bH.x, bH.y, bH.z, bH.w};
    #pragma unroll
    for (int rp = 0; rp < 4; ++rp) {
        float v[2][8];
        #pragma unroll
        for (int q = 0; q < 8; ++q) {
            float lo, hi; upk2(acc[rp][q], lo, hi);
            v[0][q] = lo + bq[q]; v[1][q] = hi + bq[q];
        }
        #pragma unroll
        for (int p = 0; p < 2; ++p) {
            const int row = r0 + x + 2 * rp + p;
            if (row < NN) {
                float* dst = out + (size_t)row * D;
                *(float4*)(dst + 4 * tx)      = make_float4(v[p][0], v[p][1], v[p][2], v[p][3]);
                *(float4*)(dst + 64 + 4 * tx) = make_float4(v[p][4], v[p][5], v[p][6], v[p][7]);
            }
        }
    }
}

// ---------------------------------------------------------------------------
// Kernel 2: fused per-key message kernel. grid = (ceil(E/128), K)
// ---------------------------------------------------------------------------
__global__ void __launch_bounds__(256, 1)
gnn_fused_kernel(const float* __restrict__ h,
                 const int*   __restrict__ pairs,
                 const float* __restrict__ degrees,
                 const int*   __restrict__ scat,
                 const float* __restrict__ W_tr, const float* __restrict__ b_tr,
                 const float* __restrict__ W_g1, const float* __restrict__ b_g1,
                 const float* __restrict__ W_g2, const float* __restrict__ b_g2,
                 const float* __restrict__ eps,
                 float* __restrict__ out)
{
    extern __shared__ float sm[];
    float* As = sm;                   // [KD1][AST] gathered ht (transposed/swizzled)
    float* Bs = As + KD1 * AST;       // [D][AST]   relu(ht@Wg1+b) (transposed/swizzled)
    float* Ws = Bs + D * AST;         // [KD1][D]   streamed weights

    const int tid = threadIdx.x;
    const int tx  = tid & 15;
    const int x   = (tid >> 4) * 8;
    const int e0  = blockIdx.x * TILE;
    const int k   = blockIdx.y;

    float prod[8][8];
    #pragma unroll
    for (int j = 0; j < 8; ++j)
        #pragma unroll
        for (int q = 0; q < 8; ++q) prod[j][q] = 1.0f;

    ull acc[4][8];

    for (int it = 0; it < NT; ++it) {
        __syncthreads();   // prior reads of As/Bs/Ws done
        // gather ht tile
        {
            const int r = tid >> 1, half = tid & 1;
            const int e = e0 + r;
            int row = -1;
            if (e < NE) row = pairs[(k * NT + it) * NE + e];
            gather_rows(As, h, row, r, half);
            if (half == 0) {           // degree features, cols 128..130 (s4 = 0)
                float d0 = 0.f, d1 = 0.f, d2 = 0.f;
                if (e < NE) {
                    const float* dg = degrees + ((size_t)(k * NT + it) * NE + e) * NOHL;
                    d0 = dg[0]; d1 = dg[1]; d2 = dg[2];
                }
                As[(D + 0) * AST + r] = d0;
                As[(D + 1) * AST + r] = d1;
                As[(D + 2) * AST + r] = d2;
            }
        }
        wcopy(Ws, W_g1 + (size_t)k * KD1 * D, KD1 * D / 4, tid);
        cp_fence();
        __syncthreads();

        // GEMM1: g1 = relu(ht @ W_g1 + b) -> Bs (transposed/swizzled)
        gemm_rp<KD1>(As, Ws, acc, x, tx);
        {
            const float* bb = b_g1 + k * D;
            const float4 bL = *(const float4*)(bb + 4 * tx);
            const float4 bH = *(const float4*)(bb + 64 + 4 * tx);
            const float bq[8] = {bL.x, bL.y, bL.z, bL.w, bH.x, bH.y, bH.z, bH.w};
            #pragma unroll
            for (int q = 0; q < 8; ++q) {
                const int c  = (q < 4) ? (4 * tx + q) : (60 + 4 * tx + q);
                const int s4 = ((c >> 3) & 7) << 2;
                float* col = Bs + c * AST;
                #pragma unroll
                for (int rp = 0; rp < 4; ++rp) {
                    float lo, hi; upk2(acc[rp][q], lo, hi);
                    const int pr = (x + 2 * rp) ^ s4;
                    *(float2*)(col + pr) = make_float2(fmaxf(lo + bq[q], 0.f),
                                                       fmaxf(hi + bq[q], 0.f));
                }
            }
        }
        __syncthreads();   // Ws reads done; Bs stores visible after next sync

        // GEMM2: prod *= sigmoid(ht @ W_tr + b)
        wcopy(Ws, W_tr + (size_t)k * KD1 * D, KD1 * D / 4, tid);
        cp_fence();
        __syncthreads();
        gemm_rp<KD1>(As, Ws, acc, x, tx);
        prod_sig(acc, prod, b_tr + k * D, tx);
        __syncthreads();   // Ws reads done

        // GEMM3: prod *= sigmoid(g1 @ W_g2 + b)
        wcopy(Ws, W_g2 + (size_t)k * D * D, D * D / 4, tid);
        cp_fence();
        __syncthreads();
        gemm_rp<D>(Bs, Ws, acc, x, tx);
        prod_sig(acc, prod, b_g2 + k * D, tx);
    }

    // scatter-add: out[scat[k,e]] += (1+eps[k]) * prod
    const float scale = 1.0f + eps[k];
    #pragma unroll
    for (int j = 0; j < 8; ++j) {
        const int e = e0 + x + j;
        if (e < NE) {
            const int idx = scat[k * NE + e];
            float* dst = out + (size_t)idx * D;
            asm volatile("red.global.add.v4.f32 [%0], {%1,%2,%3,%4};"
                         :: "l"(dst + 4 * tx),
                            "f"(prod[j][0] * scale), "f"(prod[j][1] * scale),
                            "f"(prod[j][2] * scale), "f"(prod[j][3] * scale) : "memory");
            asm volatile("red.global.add.v4.f32 [%0], {%1,%2,%3,%4};"
                         :: "l"(dst + 64 + 4 * tx),
                            "f"(prod[j][4] * scale), "f"(prod[j][5] * scale),
                            "f"(prod[j][6] * scale), "f"(prod[j][7] * scale) : "memory");
        }
    }
}

// ---------------------------------------------------------------------------
extern "C" void kernel_launch(void* const* d_in, const int* in_sizes, int n_in,
                              void* d_out, int out_size)
{
    const float* h       = (const float*)d_in[0];
    const int*   pairs   = (const int*)  d_in[1];
    const float* degrees = (const float*)d_in[2];
    const int*   scat    = (const int*)  d_in[3];
    const float* W_lin   = (const float*)d_in[4];
    const float* b_lin   = (const float*)d_in[5];
    const float* W_tr    = (const float*)d_in[6];
    const float* b_tr    = (const float*)d_in[7];
    const float* W_g1    = (const float*)d_in[8];
    const float* b_g1    = (const float*)d_in[9];
    const float* W_g2    = (const float*)d_in[10];
    const float* b_g2    = (const float*)d_in[11];
    const float* eps     = (const float*)d_in[12];
    float* out = (float*)d_out;

    cudaFuncSetAttribute(gnn_lin_kernel,
                         cudaFuncAttributeMaxDynamicSharedMemorySize, SM_LIN);
    cudaFuncSetAttribute(gnn_fused_kernel,
                         cudaFuncAttributeMaxDynamicSharedMemorySize, SM_FUSED);

    gnn_lin_kernel<<<(NN + TILE - 1) / TILE, 256, SM_LIN>>>(h, W_lin, b_lin, out);

    dim3 grid((NE + TILE - 1) / TILE, NK);
    gnn_fused_kernel<<<grid, 256, SM_FUSED>>>(h, pairs, degrees, scat,
                                              W_tr, b_tr, W_g1, b_g1,
                                              W_g2, b_g2, eps, out);
}